// round 10
// baseline (speedup 1.0000x reference)
#include <cuda_runtime.h>
#include <cuda_bf16.h>

#define NODES 100000
#define INCH  256
#define HIDC  128
#define OUTC  64
#define EDGES 1600000

// Scratch (device globals — allocation-free rule)
__device__ int   g_is64;           // edge_index dtype flag (1 = int64, 0 = int32)
__device__ float g_dinv[NODES];
__device__ int   g_rows[EDGES];
__device__ int   g_cols[EDGES];
__device__ float g_ew[EDGES];
__device__ float g_h1[NODES * (size_t)HIDC];
__device__ float g_agg1[NODES * (size_t)HIDC];
__device__ float g_h2[NODES * (size_t)OUTC];

// ---------------- dtype detection ----------------
// View edge_index as int32 words. Node IDs < 100000 << 2^31, so if the data is
// little-endian int64 every odd-indexed word is 0. If int32, odd words are
// uniform random node IDs — 2048 consecutive zeros is impossible in practice.
__global__ void k_detect_dtype(const int* __restrict__ w) {
    __shared__ int any;
    if (threadIdx.x == 0) any = 0;
    __syncthreads();
    for (int i = threadIdx.x * 2 + 1; i < 4096; i += blockDim.x * 2)
        if (w[i] != 0) any = 1;   // benign race: all writers store 1
    __syncthreads();
    if (threadIdx.x == 0) g_is64 = (any == 0);
}

// ---------------- degree / norm / edge prep ----------------
__global__ void k_init_deg(float* __restrict__ deg) {
    int i = blockIdx.x * blockDim.x + threadIdx.x;
    if (i < NODES) deg[i] = 1.0f;  // self-loop
}

// Decode edge indices (either dtype) into int32 scratch, fused w/ degree count.
__global__ void k_prep_edges(const int* __restrict__ ei, int E,
                             int* __restrict__ rows, int* __restrict__ cols,
                             float* __restrict__ deg) {
    int e = blockIdx.x * blockDim.x + threadIdx.x;
    if (e >= E) return;
    int r, c;
    if (g_is64) {                  // little-endian int64: take low words
        r = ei[2 * (size_t)e];
        c = ei[2 * ((size_t)E + e)];
    } else {                       // int32
        r = ei[e];
        c = ei[E + e];
    }
    rows[e] = r;
    cols[e] = c;
    atomicAdd(&deg[c], 1.0f);
}

__global__ void k_rsqrt_deg(float* __restrict__ deg) {
    int i = blockIdx.x * blockDim.x + threadIdx.x;
    if (i < NODES) deg[i] = rsqrtf(deg[i]);
}

// per-edge normalization weight
__global__ void k_edge_w(const int* __restrict__ rows,
                         const int* __restrict__ cols, int E,
                         const float* __restrict__ dinv,
                         float* __restrict__ ew) {
    int e = blockIdx.x * blockDim.x + threadIdx.x;
    if (e >= E) return;
    ew[e] = dinv[rows[e]] * dinv[cols[e]];
}

// ---------------- SGEMM (N == BN, single block-column) ----------------
// C[M,BN] = A[M,K] @ B[K,BN]; optional relu applied to A elements on load.
// K is compile-time -> fully unrollable outer loop, static addressing.
template <int BM, int BN, int BK, int TM, int TN, int K, bool RELU_IN>
__global__ void __launch_bounds__(256) sgemm(const float* __restrict__ A,
                                             const float* __restrict__ B,
                                             float* __restrict__ C,
                                             int M) {
    __shared__ float As[BK][BM];
    __shared__ float Bs[BK][BN];

    constexpr int THREADS = (BM / TM) * (BN / TN);
    static_assert(THREADS == 256, "thread count");
    const int tid = threadIdx.x;
    const int m0 = blockIdx.x * BM;

    const int tRow = (tid / (BN / TN)) * TM;
    const int tCol = (tid % (BN / TN)) * TN;

    float acc[TM][TN] = {};
    float ra[TM], rb[TN];

    constexpr int A_VECS = BM * BK / 4;
    constexpr int A_ITER = A_VECS / THREADS;
    constexpr int B_VECS = BK * BN / 4;
    constexpr int B_ITER = (B_VECS + THREADS - 1) / THREADS;

    for (int k0 = 0; k0 < K; k0 += BK) {
        // A tile -> smem (transposed)
        #pragma unroll
        for (int i = 0; i < A_ITER; i++) {
            int idx = tid + i * THREADS;
            int ar = idx / (BK / 4);
            int ac = (idx % (BK / 4)) * 4;
            int gr = m0 + ar;
            float4 v = make_float4(0.f, 0.f, 0.f, 0.f);
            if (gr < M) v = *(const float4*)(A + (size_t)gr * K + k0 + ac);
            if (RELU_IN) {
                v.x = fmaxf(v.x, 0.f); v.y = fmaxf(v.y, 0.f);
                v.z = fmaxf(v.z, 0.f); v.w = fmaxf(v.w, 0.f);
            }
            As[ac + 0][ar] = v.x;
            As[ac + 1][ar] = v.y;
            As[ac + 2][ar] = v.z;
            As[ac + 3][ar] = v.w;
        }
        // B tile -> smem
        #pragma unroll
        for (int i = 0; i < B_ITER; i++) {
            int idx = tid + i * THREADS;
            if (idx < B_VECS) {
                int br = idx / (BN / 4);
                int bc = (idx % (BN / 4)) * 4;
                *(float4*)&Bs[br][bc] =
                    *(const float4*)(B + (size_t)(k0 + br) * BN + bc);
            }
        }
        __syncthreads();

        #pragma unroll
        for (int k = 0; k < BK; k++) {
            #pragma unroll
            for (int i = 0; i < TM; i++) ra[i] = As[k][tRow + i];
            #pragma unroll
            for (int j = 0; j < TN; j++) rb[j] = Bs[k][tCol + j];
            #pragma unroll
            for (int i = 0; i < TM; i++)
                #pragma unroll
                for (int j = 0; j < TN; j++)
                    acc[i][j] = fmaf(ra[i], rb[j], acc[i][j]);
        }
        __syncthreads();
    }

    #pragma unroll
    for (int i = 0; i < TM; i++) {
        int gr = m0 + tRow + i;
        if (gr < M) {
            #pragma unroll
            for (int j = 0; j < TN; j += 4) {
                float4 v = make_float4(acc[i][j], acc[i][j + 1],
                                       acc[i][j + 2], acc[i][j + 3]);
                *(float4*)(C + (size_t)gr * BN + tCol + j) = v;
            }
        }
    }
}

// ---------------- aggregation layer 1 (HIDC=128) ----------------
// agg[i] = dinv[i]^2 * h1[i] + b1  (self-loop term + bias, also initializes buffer)
__global__ void k_selfloop1(const float* __restrict__ h1,
                            const float* __restrict__ dinv,
                            const float* __restrict__ b1,
                            float* __restrict__ agg) {
    int idx = blockIdx.x * blockDim.x + threadIdx.x;  // over NODES*HIDC/4
    if (idx >= NODES * (HIDC / 4)) return;
    int n = idx / (HIDC / 4);
    int c = (idx % (HIDC / 4)) * 4;
    float w = dinv[n];
    w = w * w;
    float4 h = *(const float4*)(h1 + (size_t)n * HIDC + c);
    float4 o;
    o.x = w * h.x + b1[c + 0];
    o.y = w * h.y + b1[c + 1];
    o.z = w * h.z + b1[c + 2];
    o.w = w * h.w + b1[c + 3];
    *(float4*)(agg + (size_t)n * HIDC + c) = o;
}

// one warp per edge; lane handles channels {lane, lane+32, lane+64, lane+96}
// -> every scalar RED and every gather load is a fully-coalesced 128B warp access
__global__ void k_scatter1(const int* __restrict__ rows,
                           const int* __restrict__ cols,
                           const float* __restrict__ ew, int E,
                           const float* __restrict__ h1,
                           float* __restrict__ agg) {
    int warp = (blockIdx.x * blockDim.x + threadIdx.x) >> 5;
    int lane = threadIdx.x & 31;
    if (warp >= E) return;
    int row = rows[warp];
    int col = cols[warp];
    float w = ew[warp];
    const float* hs = h1 + (size_t)row * HIDC + lane;
    float* as = agg + (size_t)col * HIDC + lane;
    #pragma unroll
    for (int i = 0; i < 4; i++) {
        atomicAdd(as + i * 32, w * hs[i * 32]);
    }
}

// ---------------- aggregation layer 2 (OUTC=64) ----------------
__global__ void k_selfloop2(const float* __restrict__ h2,
                            const float* __restrict__ dinv,
                            const float* __restrict__ b2,
                            float* __restrict__ out) {
    int idx = blockIdx.x * blockDim.x + threadIdx.x;  // over NODES*OUTC/4
    if (idx >= NODES * (OUTC / 4)) return;
    int n = idx / (OUTC / 4);
    int c = (idx % (OUTC / 4)) * 4;
    float w = dinv[n];
    w = w * w;
    float4 h = *(const float4*)(h2 + (size_t)n * OUTC + c);
    float4 o;
    o.x = w * h.x + b2[c + 0];
    o.y = w * h.y + b2[c + 1];
    o.z = w * h.z + b2[c + 2];
    o.w = w * h.w + b2[c + 3];
    *(float4*)(out + (size_t)n * OUTC + c) = o;
}

// one warp per edge; lane handles channels {lane, lane+32}
__global__ void k_scatter2(const int* __restrict__ rows,
                           const int* __restrict__ cols,
                           const float* __restrict__ ew, int E,
                           const float* __restrict__ h2,
                           float* __restrict__ out) {
    int warp = (blockIdx.x * blockDim.x + threadIdx.x) >> 5;
    int lane = threadIdx.x & 31;
    if (warp >= E) return;
    int row = rows[warp];
    int col = cols[warp];
    float w = ew[warp];
    const float* hs = h2 + (size_t)row * OUTC + lane;
    float* os = out + (size_t)col * OUTC + lane;
    #pragma unroll
    for (int i = 0; i < 2; i++) {
        atomicAdd(os + i * 32, w * hs[i * 32]);
    }
}

extern "C" void kernel_launch(void* const* d_in, const int* in_sizes, int n_in,
                              void* d_out, int out_size) {
    const float* x  = (const float*)d_in[0];
    const int*   ei = (const int*)d_in[1];   // dtype auto-detected on device
    const float* W1 = (const float*)d_in[2];
    const float* b1 = (const float*)d_in[3];
    const float* W2 = (const float*)d_in[4];
    const float* b2 = (const float*)d_in[5];
    float* out = (float*)d_out;

    const int E = in_sizes[1] / 2;

    // Resolve device-global scratch addresses once (host-side cache).
    static float *dinv = nullptr, *h1 = nullptr, *agg1 = nullptr, *h2 = nullptr,
                 *ew = nullptr;
    static int *rows = nullptr, *cols = nullptr;
    if (!dinv) {
        cudaGetSymbolAddress((void**)&dinv, g_dinv);
        cudaGetSymbolAddress((void**)&h1,   g_h1);
        cudaGetSymbolAddress((void**)&agg1, g_agg1);
        cudaGetSymbolAddress((void**)&h2,   g_h2);
        cudaGetSymbolAddress((void**)&ew,   g_ew);
        cudaGetSymbolAddress((void**)&rows, g_rows);
        cudaGetSymbolAddress((void**)&cols, g_cols);
    }

    // dtype detect + norm + edge prep
    k_detect_dtype<<<1, 256>>>(ei);
    k_init_deg<<<(NODES + 255) / 256, 256>>>(dinv);
    k_prep_edges<<<(E + 255) / 256, 256>>>(ei, E, rows, cols, dinv);
    k_rsqrt_deg<<<(NODES + 255) / 256, 256>>>(dinv);
    k_edge_w<<<(E + 255) / 256, 256>>>(rows, cols, E, dinv, ew);

    // layer 1: h1 = x @ W1
    sgemm<128, 128, 16, 8, 8, INCH, false>
        <<<(NODES + 127) / 128, 256>>>(x, W1, h1, NODES);

    // aggregate 1
    k_selfloop1<<<(NODES * (HIDC / 4) + 255) / 256, 256>>>(h1, dinv, b1, agg1);
    {
        long long threads = (long long)E * 32;
        k_scatter1<<<(unsigned)((threads + 255) / 256), 256>>>(rows, cols, ew, E, h1, agg1);
    }

    // layer 2: h2 = relu(agg1) @ W2
    sgemm<128, 64, 16, 8, 4, HIDC, true>
        <<<(NODES + 127) / 128, 256>>>(agg1, W2, h2, NODES);

    // aggregate 2 -> out
    k_selfloop2<<<(NODES * (OUTC / 4) + 255) / 256, 256>>>(h2, dinv, b2, out);
    {
        long long threads = (long long)E * 32;
        k_scatter2<<<(unsigned)((threads + 255) / 256), 256>>>(rows, cols, ew, E, h2, out);
    }
}

// round 11
// speedup vs baseline: 1.2330x; 1.2330x over previous
#include <cuda_runtime.h>
#include <cuda_bf16.h>
#include <cstdint>

#define NODES 100000
#define INCH  256
#define HIDC  128
#define OUTC  64
#define EDGES 1600000

// Scratch (device globals — allocation-free rule)
__device__ int   g_is64;           // edge_index dtype flag (1 = int64, 0 = int32)
__device__ float g_dinv[NODES];
__device__ int   g_rows[EDGES];
__device__ int   g_cols[EDGES];
__device__ float g_ew[EDGES];
__device__ float g_h1[NODES * (size_t)HIDC];
__device__ float g_agg1[NODES * (size_t)HIDC];
__device__ float g_h2[NODES * (size_t)OUTC];

// ---------------- dtype detection ----------------
__global__ void k_detect_dtype(const int* __restrict__ w) {
    __shared__ int any;
    if (threadIdx.x == 0) any = 0;
    __syncthreads();
    for (int i = threadIdx.x * 2 + 1; i < 4096; i += blockDim.x * 2)
        if (w[i] != 0) any = 1;   // benign race: all writers store 1
    __syncthreads();
    if (threadIdx.x == 0) g_is64 = (any == 0);
}

// ---------------- degree / norm / edge prep ----------------
__global__ void k_init_deg(float* __restrict__ deg) {
    int i = blockIdx.x * blockDim.x + threadIdx.x;
    if (i < NODES) deg[i] = 1.0f;  // self-loop
}

__global__ void k_prep_edges(const int* __restrict__ ei, int E,
                             int* __restrict__ rows, int* __restrict__ cols,
                             float* __restrict__ deg) {
    int e = blockIdx.x * blockDim.x + threadIdx.x;
    if (e >= E) return;
    int r, c;
    if (g_is64) {                  // little-endian int64: take low words
        r = ei[2 * (size_t)e];
        c = ei[2 * ((size_t)E + e)];
    } else {                       // int32
        r = ei[e];
        c = ei[E + e];
    }
    rows[e] = r;
    cols[e] = c;
    atomicAdd(&deg[c], 1.0f);
}

__global__ void k_rsqrt_deg(float* __restrict__ deg) {
    int i = blockIdx.x * blockDim.x + threadIdx.x;
    if (i < NODES) deg[i] = rsqrtf(deg[i]);
}

__global__ void k_edge_w(const int* __restrict__ rows,
                         const int* __restrict__ cols, int E,
                         const float* __restrict__ dinv,
                         float* __restrict__ ew) {
    int e = blockIdx.x * blockDim.x + threadIdx.x;
    if (e >= E) return;
    ew[e] = dinv[rows[e]] * dinv[cols[e]];
}

// ---------------- tf32 tensor-core GEMM ----------------
// C[M,N] = A[M,K] @ B[K,N], fp32 accumulate, optional relu on A load.
// BM=128, BN=64 per block (grid.y covers N/64), BK=32, 256 thr, 8 warps (4x2),
// warp tile 32x32 via mma.sync.m16n8k8.tf32. Double-buffered dynamic smem.
#define GBM 128
#define GBN 64
#define GBK 32
#define APAD 4   // smem row stride 36 -> conflict-free fragment reads

__device__ __forceinline__ float to_tf32(float x) {
    uint32_t u;
    asm("cvt.rna.tf32.f32 %0, %1;" : "=r"(u) : "f"(x));
    return __uint_as_float(u);
}

__device__ __forceinline__ void mma_tf32(float* c, const uint32_t* a, const uint32_t* b) {
    asm volatile(
        "mma.sync.aligned.m16n8k8.row.col.f32.tf32.tf32.f32 "
        "{%0,%1,%2,%3}, {%4,%5,%6,%7}, {%8,%9}, {%0,%1,%2,%3};\n"
        : "+f"(c[0]), "+f"(c[1]), "+f"(c[2]), "+f"(c[3])
        : "r"(a[0]), "r"(a[1]), "r"(a[2]), "r"(a[3]), "r"(b[0]), "r"(b[1]));
}

template <int N, int K, bool RELU_IN>
__global__ void __launch_bounds__(256) tf32gemm(const float* __restrict__ A,
                                                const float* __restrict__ B,
                                                float* __restrict__ C, int M) {
    extern __shared__ float smem[];
    float* As = smem;                       // [2][GBM][GBK+APAD]
    float* Bs = smem + 2 * GBM * (GBK + APAD);  // [2][GBN][GBK+APAD]
    constexpr int AST = GBK + APAD;         // 36
    constexpr int ABUF = GBM * AST;
    constexpr int BBUF = GBN * AST;
    constexpr int T = K / GBK;              // k-tiles

    const int tid  = threadIdx.x;
    const int wid  = tid >> 5;
    const int lane = tid & 31;
    const int g    = lane >> 2;             // groupID 0..7
    const int t4   = lane & 3;              // threadID_in_group 0..3
    const int warpM = (wid >> 1) * 32;      // 4 warps in M
    const int warpN = (wid & 1) * 32;       // 2 warps in N
    const int m0 = blockIdx.x * GBM;
    const int n0 = blockIdx.y * GBN;

    float acc[2][4][4] = {};
    float4 areg[4];
    float4 breg[2];

    // ---- stage loaders ----
    auto load_gmem = [&](int kt) {
        #pragma unroll
        for (int i = 0; i < 4; i++) {
            int r  = (tid >> 3) + i * 32;
            int c4 = (tid & 7) * 4;
            int gr = m0 + r;
            float4 v = make_float4(0.f, 0.f, 0.f, 0.f);
            if (gr < M) v = *(const float4*)(A + (size_t)gr * K + kt + c4);
            if (RELU_IN) {
                v.x = fmaxf(v.x, 0.f); v.y = fmaxf(v.y, 0.f);
                v.z = fmaxf(v.z, 0.f); v.w = fmaxf(v.w, 0.f);
            }
            areg[i] = v;
        }
        #pragma unroll
        for (int i = 0; i < 2; i++) {
            int k  = (tid >> 4) + i * 16;
            int n4 = (tid & 15) * 4;
            breg[i] = *(const float4*)(B + (size_t)(kt + k) * N + n0 + n4);
        }
    };
    auto store_smem = [&](int buf) {
        float* as = As + buf * ABUF;
        float* bs = Bs + buf * BBUF;
        #pragma unroll
        for (int i = 0; i < 4; i++) {
            int r  = (tid >> 3) + i * 32;
            int c4 = (tid & 7) * 4;
            float* p = as + r * AST + c4;
            p[0] = to_tf32(areg[i].x); p[1] = to_tf32(areg[i].y);
            p[2] = to_tf32(areg[i].z); p[3] = to_tf32(areg[i].w);
        }
        #pragma unroll
        for (int i = 0; i < 2; i++) {
            int k  = (tid >> 4) + i * 16;
            int n4 = (tid & 15) * 4;
            bs[(n4 + 0) * AST + k] = to_tf32(breg[i].x);
            bs[(n4 + 1) * AST + k] = to_tf32(breg[i].y);
            bs[(n4 + 2) * AST + k] = to_tf32(breg[i].z);
            bs[(n4 + 3) * AST + k] = to_tf32(breg[i].w);
        }
    };
    auto compute = [&](int buf) {
        const float* as = As + buf * ABUF + warpM * AST;
        const float* bs = Bs + buf * BBUF + warpN * AST;
        #pragma unroll
        for (int ks = 0; ks < GBK; ks += 8) {
            uint32_t af[2][4], bf[4][2];
            #pragma unroll
            for (int mt = 0; mt < 2; mt++) {
                const float* a = as + (mt * 16 + g) * AST + ks;
                af[mt][0] = __float_as_uint(a[t4]);
                af[mt][1] = __float_as_uint(a[8 * AST + t4]);
                af[mt][2] = __float_as_uint(a[t4 + 4]);
                af[mt][3] = __float_as_uint(a[8 * AST + t4 + 4]);
            }
            #pragma unroll
            for (int nt = 0; nt < 4; nt++) {
                const float* b = bs + (nt * 8 + g) * AST + ks;
                bf[nt][0] = __float_as_uint(b[t4]);
                bf[nt][1] = __float_as_uint(b[t4 + 4]);
            }
            #pragma unroll
            for (int mt = 0; mt < 2; mt++)
                #pragma unroll
                for (int nt = 0; nt < 4; nt++)
                    mma_tf32(acc[mt][nt], af[mt], bf[nt]);
        }
    };

    // ---- double-buffered mainloop ----
    load_gmem(0);
    store_smem(0);
    __syncthreads();
    #pragma unroll
    for (int t = 0; t < T; t++) {
        if (t + 1 < T) load_gmem((t + 1) * GBK);
        compute(t & 1);
        if (t + 1 < T) {
            store_smem((t + 1) & 1);
            __syncthreads();
        }
    }

    // ---- epilogue ----
    #pragma unroll
    for (int mt = 0; mt < 2; mt++) {
        int r0 = m0 + warpM + mt * 16 + g;
        #pragma unroll
        for (int nt = 0; nt < 4; nt++) {
            int cc = n0 + warpN + nt * 8 + t4 * 2;
            if (r0 < M)
                *(float2*)(C + (size_t)r0 * N + cc) =
                    make_float2(acc[mt][nt][0], acc[mt][nt][1]);
            if (r0 + 8 < M)
                *(float2*)(C + (size_t)(r0 + 8) * N + cc) =
                    make_float2(acc[mt][nt][2], acc[mt][nt][3]);
        }
    }
}

constexpr int GEMM_SMEM = (2 * GBM * (GBK + APAD) + 2 * GBN * (GBK + APAD)) * 4;

// ---------------- aggregation layer 1 (HIDC=128) ----------------
__global__ void k_selfloop1(const float* __restrict__ h1,
                            const float* __restrict__ dinv,
                            const float* __restrict__ b1,
                            float* __restrict__ agg) {
    int idx = blockIdx.x * blockDim.x + threadIdx.x;
    if (idx >= NODES * (HIDC / 4)) return;
    int n = idx / (HIDC / 4);
    int c = (idx % (HIDC / 4)) * 4;
    float w = dinv[n];
    w = w * w;
    float4 h = *(const float4*)(h1 + (size_t)n * HIDC + c);
    float4 o;
    o.x = w * h.x + b1[c + 0];
    o.y = w * h.y + b1[c + 1];
    o.z = w * h.z + b1[c + 2];
    o.w = w * h.w + b1[c + 3];
    *(float4*)(agg + (size_t)n * HIDC + c) = o;
}

// one warp per edge; lane handles channels {lane, lane+32, lane+64, lane+96}
__global__ void k_scatter1(const int* __restrict__ rows,
                           const int* __restrict__ cols,
                           const float* __restrict__ ew, int E,
                           const float* __restrict__ h1,
                           float* __restrict__ agg) {
    int warp = (blockIdx.x * blockDim.x + threadIdx.x) >> 5;
    int lane = threadIdx.x & 31;
    if (warp >= E) return;
    int row = rows[warp];
    int col = cols[warp];
    float w = ew[warp];
    const float* hs = h1 + (size_t)row * HIDC + lane;
    float* as = agg + (size_t)col * HIDC + lane;
    #pragma unroll
    for (int i = 0; i < 4; i++) {
        atomicAdd(as + i * 32, w * hs[i * 32]);
    }
}

// ---------------- aggregation layer 2 (OUTC=64) ----------------
__global__ void k_selfloop2(const float* __restrict__ h2,
                            const float* __restrict__ dinv,
                            const float* __restrict__ b2,
                            float* __restrict__ out) {
    int idx = blockIdx.x * blockDim.x + threadIdx.x;
    if (idx >= NODES * (OUTC / 4)) return;
    int n = idx / (OUTC / 4);
    int c = (idx % (OUTC / 4)) * 4;
    float w = dinv[n];
    w = w * w;
    float4 h = *(const float4*)(h2 + (size_t)n * OUTC + c);
    float4 o;
    o.x = w * h.x + b2[c + 0];
    o.y = w * h.y + b2[c + 1];
    o.z = w * h.z + b2[c + 2];
    o.w = w * h.w + b2[c + 3];
    *(float4*)(out + (size_t)n * OUTC + c) = o;
}

// one warp per edge; lane handles channels {lane, lane+32}
__global__ void k_scatter2(const int* __restrict__ rows,
                           const int* __restrict__ cols,
                           const float* __restrict__ ew, int E,
                           const float* __restrict__ h2,
                           float* __restrict__ out) {
    int warp = (blockIdx.x * blockDim.x + threadIdx.x) >> 5;
    int lane = threadIdx.x & 31;
    if (warp >= E) return;
    int row = rows[warp];
    int col = cols[warp];
    float w = ew[warp];
    const float* hs = h2 + (size_t)row * OUTC + lane;
    float* os = out + (size_t)col * OUTC + lane;
    #pragma unroll
    for (int i = 0; i < 2; i++) {
        atomicAdd(os + i * 32, w * hs[i * 32]);
    }
}

extern "C" void kernel_launch(void* const* d_in, const int* in_sizes, int n_in,
                              void* d_out, int out_size) {
    const float* x  = (const float*)d_in[0];
    const int*   ei = (const int*)d_in[1];   // dtype auto-detected on device
    const float* W1 = (const float*)d_in[2];
    const float* b1 = (const float*)d_in[3];
    const float* W2 = (const float*)d_in[4];
    const float* b2 = (const float*)d_in[5];
    float* out = (float*)d_out;

    const int E = in_sizes[1] / 2;

    static float *dinv = nullptr, *h1 = nullptr, *agg1 = nullptr, *h2 = nullptr,
                 *ew = nullptr;
    static int *rows = nullptr, *cols = nullptr;
    if (!dinv) {
        cudaGetSymbolAddress((void**)&dinv, g_dinv);
        cudaGetSymbolAddress((void**)&h1,   g_h1);
        cudaGetSymbolAddress((void**)&agg1, g_agg1);
        cudaGetSymbolAddress((void**)&h2,   g_h2);
        cudaGetSymbolAddress((void**)&ew,   g_ew);
        cudaGetSymbolAddress((void**)&rows, g_rows);
        cudaGetSymbolAddress((void**)&cols, g_cols);
        cudaFuncSetAttribute(tf32gemm<HIDC, INCH, false>,
                             cudaFuncAttributeMaxDynamicSharedMemorySize, GEMM_SMEM);
        cudaFuncSetAttribute(tf32gemm<OUTC, HIDC, true>,
                             cudaFuncAttributeMaxDynamicSharedMemorySize, GEMM_SMEM);
    }

    // dtype detect + norm + edge prep
    k_detect_dtype<<<1, 256>>>(ei);
    k_init_deg<<<(NODES + 255) / 256, 256>>>(dinv);
    k_prep_edges<<<(E + 255) / 256, 256>>>(ei, E, rows, cols, dinv);
    k_rsqrt_deg<<<(NODES + 255) / 256, 256>>>(dinv);
    k_edge_w<<<(E + 255) / 256, 256>>>(rows, cols, E, dinv, ew);

    // layer 1: h1 = x @ W1  (tf32 tensor cores)
    {
        dim3 grid((NODES + GBM - 1) / GBM, HIDC / GBN);
        tf32gemm<HIDC, INCH, false><<<grid, 256, GEMM_SMEM>>>(x, W1, h1, NODES);
    }

    // aggregate 1
    k_selfloop1<<<(NODES * (HIDC / 4) + 255) / 256, 256>>>(h1, dinv, b1, agg1);
    {
        long long threads = (long long)E * 32;
        k_scatter1<<<(unsigned)((threads + 255) / 256), 256>>>(rows, cols, ew, E, h1, agg1);
    }

    // layer 2: h2 = relu(agg1) @ W2  (tf32 tensor cores, relu fused on A load)
    {
        dim3 grid((NODES + GBM - 1) / GBM, OUTC / GBN);
        tf32gemm<OUTC, HIDC, true><<<grid, 256, GEMM_SMEM>>>(agg1, W2, h2, NODES);
    }

    // aggregate 2 -> out
    k_selfloop2<<<(NODES * (OUTC / 4) + 255) / 256, 256>>>(h2, dinv, b2, out);
    {
        long long threads = (long long)E * 32;
        k_scatter2<<<(unsigned)((threads + 255) / 256), 256>>>(rows, cols, ew, E, h2, out);
    }
}

// round 14
// speedup vs baseline: 2.0922x; 1.6968x over previous
#include <cuda_runtime.h>
#include <cuda_bf16.h>
#include <cstdint>

#define NODES 100000
#define INCH  256
#define HIDC  128
#define OUTC  64
#define EDGES 1600000

// Scratch (device globals — allocation-free rule)
__device__ int   g_is64;
__device__ int   g_cursor;
__device__ int   g_indeg[NODES];
__device__ int   g_off[NODES];
__device__ int   g_fill[NODES];
__device__ float g_dinv[NODES];
__device__ int   g_rows[EDGES];
__device__ int   g_cols[EDGES];
__device__ int   g_csr_src[EDGES];
__device__ float g_csr_w[EDGES];
__device__ float g_h1[NODES * (size_t)HIDC];
__device__ float g_agg1[NODES * (size_t)HIDC];
__device__ float g_h2[NODES * (size_t)OUTC];

// ---------------- dtype detection ----------------
__global__ void k_detect_dtype(const int* __restrict__ w) {
    __shared__ int any;
    if (threadIdx.x == 0) any = 0;
    __syncthreads();
    for (int i = threadIdx.x * 2 + 1; i < 4096; i += blockDim.x * 2)
        if (w[i] != 0) any = 1;
    __syncthreads();
    if (threadIdx.x == 0) g_is64 = (any == 0);
}

// ---------------- CSR build ----------------
__global__ void k_init(int* __restrict__ indeg) {
    int i = blockIdx.x * blockDim.x + threadIdx.x;
    if (i < NODES) indeg[i] = 0;
    if (i == 0) g_cursor = 0;
}

__global__ void k_prep_edges(const int* __restrict__ ei, int E,
                             int* __restrict__ rows, int* __restrict__ cols,
                             int* __restrict__ indeg) {
    int e = blockIdx.x * blockDim.x + threadIdx.x;
    if (e >= E) return;
    int r, c;
    if (g_is64) {                  // little-endian int64: take low words
        r = ei[2 * (size_t)e];
        c = ei[2 * ((size_t)E + e)];
    } else {                       // int32
        r = ei[e];
        c = ei[E + e];
    }
    rows[e] = r;
    cols[e] = c;
    atomicAdd(&indeg[c], 1);
}

__global__ void k_dinv(const int* __restrict__ indeg, float* __restrict__ dinv) {
    int i = blockIdx.x * blockDim.x + threadIdx.x;
    if (i < NODES) dinv[i] = rsqrtf(1.0f + (float)indeg[i]);
}

// Disjoint per-node CSR ranges: intra-block exclusive scan + one atomic
// block reservation (391 serialized L2 atomics total — negligible).
__global__ void k_scan_off(const int* __restrict__ indeg,
                           int* __restrict__ off, int* __restrict__ fill) {
    __shared__ int s[256];
    __shared__ int base;
    int i = blockIdx.x * blockDim.x + threadIdx.x;
    int v = (i < NODES) ? indeg[i] : 0;
    s[threadIdx.x] = v;
    __syncthreads();
    // Hillis-Steele inclusive scan
    #pragma unroll
    for (int d = 1; d < 256; d <<= 1) {
        int t = (threadIdx.x >= d) ? s[threadIdx.x - d] : 0;
        __syncthreads();
        s[threadIdx.x] += t;
        __syncthreads();
    }
    if (threadIdx.x == 255) base = atomicAdd(&g_cursor, s[255]);
    __syncthreads();
    if (i < NODES) {
        off[i] = base + s[threadIdx.x] - v;   // exclusive
        fill[i] = 0;
    }
}

__global__ void k_fill(const int* __restrict__ rows, const int* __restrict__ cols,
                       int E, const int* __restrict__ off, int* __restrict__ fill,
                       const float* __restrict__ dinv,
                       int* __restrict__ csr_src, float* __restrict__ csr_w) {
    int e = blockIdx.x * blockDim.x + threadIdx.x;
    if (e >= E) return;
    int r = rows[e];
    int c = cols[e];
    int p = off[c] + atomicAdd(&fill[c], 1);
    csr_src[p] = r;
    csr_w[p] = dinv[r] * dinv[c];
}

// ---------------- tf32 tensor-core GEMM ----------------
#define GBM 128
#define GBN 64
#define GBK 32
#define APAD 4

__device__ __forceinline__ float to_tf32(float x) {
    uint32_t u;
    asm("cvt.rna.tf32.f32 %0, %1;" : "=r"(u) : "f"(x));
    return __uint_as_float(u);
}

__device__ __forceinline__ void mma_tf32(float* c, const uint32_t* a, const uint32_t* b) {
    asm volatile(
        "mma.sync.aligned.m16n8k8.row.col.f32.tf32.tf32.f32 "
        "{%0,%1,%2,%3}, {%4,%5,%6,%7}, {%8,%9}, {%0,%1,%2,%3};\n"
        : "+f"(c[0]), "+f"(c[1]), "+f"(c[2]), "+f"(c[3])
        : "r"(a[0]), "r"(a[1]), "r"(a[2]), "r"(a[3]), "r"(b[0]), "r"(b[1]));
}

template <int N, int K, bool RELU_IN>
__global__ void __launch_bounds__(256) tf32gemm(const float* __restrict__ A,
                                                const float* __restrict__ B,
                                                float* __restrict__ C, int M) {
    extern __shared__ float smem[];
    float* As = smem;
    float* Bs = smem + 2 * GBM * (GBK + APAD);
    constexpr int AST = GBK + APAD;
    constexpr int ABUF = GBM * AST;
    constexpr int BBUF = GBN * AST;
    constexpr int T = K / GBK;

    const int tid  = threadIdx.x;
    const int wid  = tid >> 5;
    const int lane = tid & 31;
    const int g    = lane >> 2;
    const int t4   = lane & 3;
    const int warpM = (wid >> 1) * 32;
    const int warpN = (wid & 1) * 32;
    const int m0 = blockIdx.x * GBM;
    const int n0 = blockIdx.y * GBN;

    float acc[2][4][4] = {};
    float4 areg[4];
    float4 breg[2];

    auto load_gmem = [&](int kt) {
        #pragma unroll
        for (int i = 0; i < 4; i++) {
            int r  = (tid >> 3) + i * 32;
            int c4 = (tid & 7) * 4;
            int gr = m0 + r;
            float4 v = make_float4(0.f, 0.f, 0.f, 0.f);
            if (gr < M) v = *(const float4*)(A + (size_t)gr * K + kt + c4);
            if (RELU_IN) {
                v.x = fmaxf(v.x, 0.f); v.y = fmaxf(v.y, 0.f);
                v.z = fmaxf(v.z, 0.f); v.w = fmaxf(v.w, 0.f);
            }
            areg[i] = v;
        }
        #pragma unroll
        for (int i = 0; i < 2; i++) {
            int k  = (tid >> 4) + i * 16;
            int n4 = (tid & 15) * 4;
            breg[i] = *(const float4*)(B + (size_t)(kt + k) * N + n0 + n4);
        }
    };
    auto store_smem = [&](int buf) {
        float* as = As + buf * ABUF;
        float* bs = Bs + buf * BBUF;
        #pragma unroll
        for (int i = 0; i < 4; i++) {
            int r  = (tid >> 3) + i * 32;
            int c4 = (tid & 7) * 4;
            float* p = as + r * AST + c4;
            p[0] = to_tf32(areg[i].x); p[1] = to_tf32(areg[i].y);
            p[2] = to_tf32(areg[i].z); p[3] = to_tf32(areg[i].w);
        }
        #pragma unroll
        for (int i = 0; i < 2; i++) {
            int k  = (tid >> 4) + i * 16;
            int n4 = (tid & 15) * 4;
            bs[(n4 + 0) * AST + k] = to_tf32(breg[i].x);
            bs[(n4 + 1) * AST + k] = to_tf32(breg[i].y);
            bs[(n4 + 2) * AST + k] = to_tf32(breg[i].z);
            bs[(n4 + 3) * AST + k] = to_tf32(breg[i].w);
        }
    };
    auto compute = [&](int buf) {
        const float* as = As + buf * ABUF + warpM * AST;
        const float* bs = Bs + buf * BBUF + warpN * AST;
        #pragma unroll
        for (int ks = 0; ks < GBK; ks += 8) {
            uint32_t af[2][4], bf[4][2];
            #pragma unroll
            for (int mt = 0; mt < 2; mt++) {
                const float* a = as + (mt * 16 + g) * AST + ks;
                af[mt][0] = __float_as_uint(a[t4]);
                af[mt][1] = __float_as_uint(a[8 * AST + t4]);
                af[mt][2] = __float_as_uint(a[t4 + 4]);
                af[mt][3] = __float_as_uint(a[8 * AST + t4 + 4]);
            }
            #pragma unroll
            for (int nt = 0; nt < 4; nt++) {
                const float* b = bs + (nt * 8 + g) * AST + ks;
                bf[nt][0] = __float_as_uint(b[t4]);
                bf[nt][1] = __float_as_uint(b[t4 + 4]);
            }
            #pragma unroll
            for (int mt = 0; mt < 2; mt++)
                #pragma unroll
                for (int nt = 0; nt < 4; nt++)
                    mma_tf32(acc[mt][nt], af[mt], bf[nt]);
        }
    };

    load_gmem(0);
    store_smem(0);
    __syncthreads();
    #pragma unroll
    for (int t = 0; t < T; t++) {
        if (t + 1 < T) load_gmem((t + 1) * GBK);
        compute(t & 1);
        if (t + 1 < T) {
            store_smem((t + 1) & 1);
            __syncthreads();
        }
    }

    #pragma unroll
    for (int mt = 0; mt < 2; mt++) {
        int r0 = m0 + warpM + mt * 16 + g;
        #pragma unroll
        for (int nt = 0; nt < 4; nt++) {
            int cc = n0 + warpN + nt * 8 + t4 * 2;
            if (r0 < M)
                *(float2*)(C + (size_t)r0 * N + cc) =
                    make_float2(acc[mt][nt][0], acc[mt][nt][1]);
            if (r0 + 8 < M)
                *(float2*)(C + (size_t)(r0 + 8) * N + cc) =
                    make_float2(acc[mt][nt][2], acc[mt][nt][3]);
        }
    }
}

constexpr int GEMM_SMEM = (2 * GBM * (GBK + APAD) + 2 * GBN * (GBK + APAD)) * 4;

// ---------------- pull aggregation (no atomics) ----------------
// One warp per node: acc = dinv^2*h[n] + b  (selfloop fused), then
// acc += w_e * h[src_e] over the node's CSR in-edges; one coalesced store.
// CH/32 channels per lane (channels {lane, lane+32, ...}).
template <int CH>
__global__ void k_agg(const int* __restrict__ off, const int* __restrict__ indeg,
                      const int* __restrict__ csr_src, const float* __restrict__ csr_w,
                      const float* __restrict__ dinv, const float* __restrict__ bias,
                      const float* __restrict__ h, float* __restrict__ o) {
    constexpr int R = CH / 32;
    int n = (blockIdx.x * blockDim.x + threadIdx.x) >> 5;
    int lane = threadIdx.x & 31;
    if (n >= NODES) return;

    float w2 = dinv[n];
    w2 = w2 * w2;
    float acc[R];
    const float* hn = h + (size_t)n * CH + lane;
    #pragma unroll
    for (int j = 0; j < R; j++) acc[j] = w2 * hn[j * 32] + bias[lane + j * 32];

    int base = off[n];
    int len = indeg[n];
    for (int i = 0; i < len; i++) {
        int s = csr_src[base + i];         // broadcast
        float w = csr_w[base + i];         // broadcast
        const float* hs = h + (size_t)s * CH + lane;
        #pragma unroll
        for (int j = 0; j < R; j++) acc[j] = fmaf(w, hs[j * 32], acc[j]);
    }

    float* on = o + (size_t)n * CH + lane;
    #pragma unroll
    for (int j = 0; j < R; j++) on[j * 32] = acc[j];
}

extern "C" void kernel_launch(void* const* d_in, const int* in_sizes, int n_in,
                              void* d_out, int out_size) {
    const float* x  = (const float*)d_in[0];
    const int*   ei = (const int*)d_in[1];   // dtype auto-detected on device
    const float* W1 = (const float*)d_in[2];
    const float* b1 = (const float*)d_in[3];
    const float* W2 = (const float*)d_in[4];
    const float* b2 = (const float*)d_in[5];
    float* out = (float*)d_out;

    const int E = in_sizes[1] / 2;

    static float *dinv = nullptr, *h1 = nullptr, *agg1 = nullptr, *h2 = nullptr,
                 *csr_w = nullptr;
    static int *rows = nullptr, *cols = nullptr, *indeg = nullptr,
               *off = nullptr, *fill = nullptr, *csr_src = nullptr;
    if (!dinv) {
        cudaGetSymbolAddress((void**)&dinv,    g_dinv);
        cudaGetSymbolAddress((void**)&h1,      g_h1);
        cudaGetSymbolAddress((void**)&agg1,    g_agg1);
        cudaGetSymbolAddress((void**)&h2,      g_h2);
        cudaGetSymbolAddress((void**)&rows,    g_rows);
        cudaGetSymbolAddress((void**)&cols,    g_cols);
        cudaGetSymbolAddress((void**)&indeg,   g_indeg);
        cudaGetSymbolAddress((void**)&off,     g_off);
        cudaGetSymbolAddress((void**)&fill,    g_fill);
        cudaGetSymbolAddress((void**)&csr_src, g_csr_src);
        cudaGetSymbolAddress((void**)&csr_w,   g_csr_w);
        cudaFuncSetAttribute(tf32gemm<HIDC, INCH, false>,
                             cudaFuncAttributeMaxDynamicSharedMemorySize, GEMM_SMEM);
        cudaFuncSetAttribute(tf32gemm<OUTC, HIDC, true>,
                             cudaFuncAttributeMaxDynamicSharedMemorySize, GEMM_SMEM);
    }

    const int NB = (NODES + 255) / 256;
    const int EB = (E + 255) / 256;

    // CSR build
    k_detect_dtype<<<1, 256>>>(ei);
    k_init<<<NB, 256>>>(indeg);
    k_prep_edges<<<EB, 256>>>(ei, E, rows, cols, indeg);
    k_dinv<<<NB, 256>>>(indeg, dinv);
    k_scan_off<<<NB, 256>>>(indeg, off, fill);
    k_fill<<<EB, 256>>>(rows, cols, E, off, fill, dinv, csr_src, csr_w);

    // layer 1: h1 = x @ W1 (tf32), then pull-aggregate (selfloop+bias fused)
    {
        dim3 grid((NODES + GBM - 1) / GBM, HIDC / GBN);
        tf32gemm<HIDC, INCH, false><<<grid, 256, GEMM_SMEM>>>(x, W1, h1, NODES);
    }
    k_agg<HIDC><<<(NODES * 32 + 255) / 256, 256>>>(off, indeg, csr_src, csr_w,
                                                   dinv, b1, h1, agg1);

    // layer 2: h2 = relu(agg1) @ W2 (tf32), then pull-aggregate -> out
    {
        dim3 grid((NODES + GBM - 1) / GBM, OUTC / GBN);
        tf32gemm<OUTC, HIDC, true><<<grid, 256, GEMM_SMEM>>>(agg1, W2, h2, NODES);
    }
    k_agg<OUTC><<<(NODES * 32 + 255) / 256, 256>>>(off, indeg, csr_src, csr_w,
                                                   dinv, b2, h2, out);
}